// round 2
// baseline (speedup 1.0000x reference)
#include <cuda_runtime.h>
#include <math.h>

// ---------------- problem constants ----------------
#define D_   768
#define K_   12
#define B_   32
#define N_   1369
#define T_   3
#define H_   8
#define HD_  96
#define BNROWS (B_*N_)

#define SCALE_     0.03608439182435161f   // 768^-0.5
#define HSCALE_    0.10206207261596575f   // 96^-0.5
#define EPS_       1e-8f

// ---------------- scratch (device global, allocation-free) ----------------
static __host__ __device__ constexpr size_t SZ_BND = (size_t)B_*N_*D_;   // 33,644,544
static __host__ __device__ constexpr size_t SZ_BKD = (size_t)B_*K_*D_;   // 294,912

static constexpr size_t O_FNORM = 0;
static constexpr size_t O_KF    = O_FNORM + SZ_BND;
static constexpr size_t O_VF    = O_KF    + SZ_BND;
static constexpr size_t O_SLOTS = O_VF    + SZ_BND;
static constexpr size_t O_SN    = O_SLOTS + SZ_BKD;
static constexpr size_t O_Q     = O_SN    + SZ_BKD;
static constexpr size_t O_UPD   = O_Q     + SZ_BKD;
static constexpr size_t O_H1    = O_UPD   + SZ_BKD;
static constexpr size_t O_O     = O_H1    + SZ_BKD;
static constexpr size_t O_RESID = O_O     + SZ_BKD;
static constexpr size_t O_H2    = O_RESID + SZ_BKD;
static constexpr size_t O_H3    = O_H2    + SZ_BKD;
static constexpr size_t O_QKV   = O_H3    + SZ_BKD;                        // B*K*3D
static constexpr size_t O_HID   = O_QKV   + (size_t)B_*K_*3*D_;            // B*K*4D
static constexpr size_t O_ATTN  = O_HID   + (size_t)B_*K_*4*D_;            // B*N*K
static constexpr size_t O_MASS  = O_ATTN  + (size_t)B_*N_*K_;
static constexpr size_t TOTALF  = O_MASS + 512;

__device__ float g_buf[TOTALF];

// ---------------- LayerNorm (optionally fused 2-input add) ----------------
__global__ void ln_kernel(const float* __restrict__ x, const float* __restrict__ x2,
                          const float* __restrict__ g, const float* __restrict__ bta,
                          float* __restrict__ out)
{
    __shared__ float row[D_];
    __shared__ float red[256];
    int r = blockIdx.x;
    int tid = threadIdx.x;
    const float* xr = x + (size_t)r * D_;
    float s = 0.f;
    for (int i = tid; i < D_; i += 256) {
        float v = xr[i];
        if (x2) v += x2[(size_t)r * D_ + i];
        row[i] = v; s += v;
    }
    red[tid] = s; __syncthreads();
    for (int o = 128; o > 0; o >>= 1) { if (tid < o) red[tid] += red[tid + o]; __syncthreads(); }
    float mean = red[0] * (1.f / D_);
    __syncthreads();
    s = 0.f;
    for (int i = tid; i < D_; i += 256) { float d = row[i] - mean; s += d * d; }
    red[tid] = s; __syncthreads();
    for (int o = 128; o > 0; o >>= 1) { if (tid < o) red[tid] += red[tid + o]; __syncthreads(); }
    float rstd = rsqrtf(red[0] * (1.f / D_) + 1e-5f);
    for (int i = tid; i < D_; i += 256)
        out[(size_t)r * D_ + i] = (row[i] - mean) * rstd * g[i] + bta[i];
}

// ---------------- tiled SGEMM: C = A[MxK] @ W[KxN] (+bias)(gelu)(+res) ----------------
// BN=64, BK=16, TN=4 fixed; BM/TM templated. 256 threads.
template<int BM, int TM>
__global__ void sgemm_kernel(const float* __restrict__ A, const float* __restrict__ W,
                             const float* __restrict__ bias, const float* __restrict__ res,
                             float* __restrict__ C, int M, int N, int K, int act)
{
    constexpr int BN = 64, BK = 16, TN = 4;
    __shared__ float As[BK][BM + 4];
    __shared__ float Bs[BK][BN];
    int tid = threadIdx.x;
    int tx = tid & 15, ty = tid >> 4;
    int m0 = blockIdx.y * BM, n0 = blockIdx.x * BN;

    float acc[TM][TN];
    #pragma unroll
    for (int i = 0; i < TM; i++)
        #pragma unroll
        for (int j = 0; j < TN; j++) acc[i][j] = 0.f;

    for (int k0 = 0; k0 < K; k0 += BK) {
        // A tile (BM x BK), vectorized, stored transposed
        #pragma unroll
        for (int i = tid; i < BM * BK / 4; i += 256) {
            int r = i >> 2, c4 = (i & 3) * 4;
            float4 v = make_float4(0.f, 0.f, 0.f, 0.f);
            if (m0 + r < M) v = *(const float4*)(A + (size_t)(m0 + r) * K + k0 + c4);
            As[c4 + 0][r] = v.x; As[c4 + 1][r] = v.y; As[c4 + 2][r] = v.z; As[c4 + 3][r] = v.w;
        }
        // B tile (BK x BN)
        #pragma unroll
        for (int p = 0; p < 4; p++) {
            int r = (tid >> 6) + p * 4, c = tid & 63;
            Bs[r][c] = (n0 + c < N) ? W[(size_t)(k0 + r) * N + n0 + c] : 0.f;
        }
        __syncthreads();
        #pragma unroll
        for (int kk = 0; kk < BK; kk++) {
            float a[TM], bv[TN];
            #pragma unroll
            for (int i = 0; i < TM; i += 4) {
                float4 t4 = *(const float4*)&As[kk][ty * TM + i];
                a[i] = t4.x; a[i + 1] = t4.y; a[i + 2] = t4.z; a[i + 3] = t4.w;
            }
            float4 b4 = *(const float4*)&Bs[kk][tx * TN];
            bv[0] = b4.x; bv[1] = b4.y; bv[2] = b4.z; bv[3] = b4.w;
            #pragma unroll
            for (int i = 0; i < TM; i++)
                #pragma unroll
                for (int j = 0; j < TN; j++) acc[i][j] += a[i] * bv[j];
        }
        __syncthreads();
    }

    #pragma unroll
    for (int i = 0; i < TM; i++) {
        int m = m0 + ty * TM + i;
        if (m >= M) continue;
        #pragma unroll
        for (int j = 0; j < TN; j++) {
            int n = n0 + tx * TN + j;
            if (n >= N) continue;
            float v = acc[i][j];
            if (bias) v += bias[n];
            if (act)  v = 0.5f * v * (1.f + erff(v * 0.70710678118654752f));
            if (res)  v += res[(size_t)m * N + n];
            C[(size_t)m * N + n] = v;
        }
    }
}

// ---------------- slot<->feature attention: logits + softmax(K) + mass ----------------
// grid (ceil(N/128), B), 128 threads; one thread per feature n.
__global__ void attn_kernel(const float* __restrict__ q, const float* __restrict__ Kf,
                            float* __restrict__ attn, float* __restrict__ mass)
{
    int b = blockIdx.y;
    int tid = threadIdx.x;
    int n0 = blockIdx.x * 128;
    int n = n0 + tid;
    __shared__ float qs[K_][D_];      // 36 KB
    __shared__ float kt[128][12];     // d-chunk 8, pad to 12 (6 KB)
    __shared__ float smass[K_];

    for (int i = tid; i < K_ * D_; i += 128) qs[i / D_][i % D_] = q[(size_t)b * K_ * D_ + i];
    if (tid < K_) smass[tid] = 0.f;
    __syncthreads();

    float acc[K_];
    #pragma unroll
    for (int s = 0; s < K_; s++) acc[s] = 0.f;

    const float* Kb = Kf + (size_t)b * N_ * D_;
    bool valid = (n < N_);

    for (int d0 = 0; d0 < D_; d0 += 8) {
        // stage K tile [128n x 8d]
        #pragma unroll
        for (int i = tid; i < 256; i += 128) {
            int r = i >> 1, c4 = (i & 1) * 4;
            float4 v = make_float4(0.f, 0.f, 0.f, 0.f);
            if (n0 + r < N_) v = *(const float4*)(Kb + (size_t)(n0 + r) * D_ + d0 + c4);
            kt[r][c4] = v.x; kt[r][c4 + 1] = v.y; kt[r][c4 + 2] = v.z; kt[r][c4 + 3] = v.w;
        }
        __syncthreads();
        if (valid) {
            #pragma unroll
            for (int c = 0; c < 8; c += 4) {
                float4 kv = *(const float4*)&kt[tid][c];
                #pragma unroll
                for (int s = 0; s < K_; s++) {
                    float4 qv = *(const float4*)&qs[s][d0 + c];
                    acc[s] += qv.x * kv.x + qv.y * kv.y + qv.z * kv.z + qv.w * kv.w;
                }
            }
        }
        __syncthreads();
    }

    if (valid) {
        float mx = -1e30f;
        #pragma unroll
        for (int s = 0; s < K_; s++) { acc[s] *= SCALE_; mx = fmaxf(mx, acc[s]); }
        float ssum = 0.f;
        #pragma unroll
        for (int s = 0; s < K_; s++) { float e = expf(acc[s] - mx); acc[s] = e; ssum += e; }
        float inv = 1.f / ssum;
        float* ap = attn + ((size_t)b * N_ + n) * K_;
        #pragma unroll
        for (int s = 0; s < K_; s++) {
            float a = acc[s] * inv;
            ap[s] = a;
            atomicAdd(&smass[s], a);
        }
    }
    __syncthreads();
    if (tid < K_) atomicAdd(&mass[b * K_ + tid], smass[tid]);
}

// ---------------- updates = (attn^T @ Vf) / max(mass, EPS) ----------------
// grid (D/128, B), 128 threads; thread owns one d.
__global__ void updates_kernel(const float* __restrict__ attn, const float* __restrict__ Vf,
                               const float* __restrict__ mass, float* __restrict__ upd)
{
    int b = blockIdx.y;
    int d = blockIdx.x * 128 + threadIdx.x;
    __shared__ float as_[32][K_];
    float acc[K_];
    #pragma unroll
    for (int s = 0; s < K_; s++) acc[s] = 0.f;
    const float* Vb = Vf + (size_t)b * N_ * D_;
    const float* Ab = attn + (size_t)b * N_ * K_;
    for (int n0 = 0; n0 < N_; n0 += 32) {
        int lim = min(32, N_ - n0);
        for (int i = threadIdx.x; i < lim * K_; i += 128) as_[i / K_][i % K_] = Ab[(size_t)n0 * K_ + i];
        __syncthreads();
        for (int r = 0; r < lim; r++) {
            float v = Vb[(size_t)(n0 + r) * D_ + d];
            #pragma unroll
            for (int s = 0; s < K_; s++) acc[s] += as_[r][s] * v;
        }
        __syncthreads();
    }
    #pragma unroll
    for (int s = 0; s < K_; s++)
        upd[((size_t)b * K_ + s) * D_ + d] = acc[s] / fmaxf(mass[b * K_ + s], EPS_);
}

// ---------------- transformer block self-attention over K=12 slots ----------------
// grid (H, B), 128 threads.
__global__ void slot_attn_kernel(const float* __restrict__ qkv, float* __restrict__ o)
{
    int h = blockIdx.x, b = blockIdx.y;
    __shared__ float qh[K_][HD_], kh[K_][HD_], vh[K_][HD_];
    __shared__ float sc[K_][K_ + 1];
    int tid = threadIdx.x;
    for (int i = tid; i < K_ * HD_; i += 128) {
        int s = i / HD_, c = i % HD_;
        const float* base = qkv + ((size_t)(b * K_ + s)) * (3 * D_) + h * HD_ + c;
        qh[s][c] = base[0]; kh[s][c] = base[D_]; vh[s][c] = base[2 * D_];
    }
    __syncthreads();
    // FIX: K_*K_ = 144 > 128 threads — must loop, not guard.
    for (int i = tid; i < K_ * K_; i += 128) {
        int si = i / K_, sj = i % K_;
        float d = 0.f;
        #pragma unroll 8
        for (int c = 0; c < HD_; c++) d += qh[si][c] * kh[sj][c];
        sc[si][sj] = d * HSCALE_;
    }
    __syncthreads();
    if (tid < K_) {
        float mx = -1e30f;
        for (int j = 0; j < K_; j++) mx = fmaxf(mx, sc[tid][j]);
        float s = 0.f;
        for (int j = 0; j < K_; j++) { float e = expf(sc[tid][j] - mx); sc[tid][j] = e; s += e; }
        float inv = 1.f / s;
        for (int j = 0; j < K_; j++) sc[tid][j] *= inv;
    }
    __syncthreads();
    for (int i = tid; i < K_ * HD_; i += 128) {
        int s = i / HD_, c = i % HD_;
        float acc = 0.f;
        #pragma unroll
        for (int j = 0; j < K_; j++) acc += sc[s][j] * vh[j][c];
        o[((size_t)(b * K_ + s)) * D_ + h * HD_ + c] = acc;
    }
}

__global__ void zero_kernel(float* __restrict__ p, int n)
{
    int i = blockIdx.x * 256 + threadIdx.x;
    if (i < n) p[i] = 0.f;
}

// ---------------- host-side launch helpers ----------------
static inline void sgemm_big(const float* A, const float* W, const float* bias, const float* res,
                             float* C, int M, int N, int K, int act)
{
    dim3 g((N + 63) / 64, (M + 127) / 128);
    sgemm_kernel<128, 8><<<g, 256>>>(A, W, bias, res, C, M, N, K, act);
}
static inline void sgemm_sm(const float* A, const float* W, const float* bias, const float* res,
                            float* C, int M, int N, int K, int act)
{
    dim3 g((N + 63) / 64, (M + 63) / 64);
    sgemm_kernel<64, 4><<<g, 256>>>(A, W, bias, res, C, M, N, K, act);
}

extern "C" void kernel_launch(void* const* d_in, const int* in_sizes, int n_in,
                              void* d_out, int out_size)
{
    const float* features   = (const float*)d_in[0];
    const float* slots_init = (const float*)d_in[1];
    const float* nf_g = (const float*)d_in[2];
    const float* nf_b = (const float*)d_in[3];
    const float* ns_g = (const float*)d_in[4];
    const float* ns_b = (const float*)d_in[5];
    const float* Wq   = (const float*)d_in[6];
    const float* Wk   = (const float*)d_in[7];
    const float* Wv   = (const float*)d_in[8];
    const float* mg   = (const float*)d_in[9];
    const float* mb   = (const float*)d_in[10];
    const float* mW1  = (const float*)d_in[11];
    const float* mb1  = (const float*)d_in[12];
    const float* mW2  = (const float*)d_in[13];
    const float* mb2  = (const float*)d_in[14];
    const float* b_ln1g = (const float*)d_in[15];
    const float* b_ln1b = (const float*)d_in[16];
    const float* b_Wqkv = (const float*)d_in[17];
    const float* b_bqkv = (const float*)d_in[18];
    const float* b_Wo   = (const float*)d_in[19];
    const float* b_bo   = (const float*)d_in[20];
    const float* b_ln2g = (const float*)d_in[21];
    const float* b_ln2b = (const float*)d_in[22];
    const float* b_W1   = (const float*)d_in[23];
    const float* b_b1   = (const float*)d_in[24];
    const float* b_W2   = (const float*)d_in[25];
    const float* b_b2   = (const float*)d_in[26];

    float* buf = nullptr;
    cudaGetSymbolAddress((void**)&buf, g_buf);
    float* fnorm = buf + O_FNORM;
    float* Kf    = buf + O_KF;
    float* Vf    = buf + O_VF;
    float* slots = buf + O_SLOTS;
    float* sn    = buf + O_SN;
    float* q     = buf + O_Q;
    float* upd   = buf + O_UPD;
    float* h1    = buf + O_H1;
    float* op    = buf + O_O;
    float* resid = buf + O_RESID;
    float* h2    = buf + O_H2;
    float* h3    = buf + O_H3;
    float* qkvp  = buf + O_QKV;
    float* hid   = buf + O_HID;
    float* attnp = buf + O_ATTN;
    float* massp = buf + O_MASS;

    // ---- loop-invariant precompute: fn = LN(features); Kf = fn@Wk; Vf = fn@Wv ----
    ln_kernel<<<BNROWS, 256>>>(features, nullptr, nf_g, nf_b, fnorm);
    sgemm_big(fnorm, Wk, nullptr, nullptr, Kf, BNROWS, D_, D_, 0);
    sgemm_big(fnorm, Wv, nullptr, nullptr, Vf, BNROWS, D_, D_, 0);
    cudaMemcpyAsync(slots, slots_init, SZ_BKD * sizeof(float), cudaMemcpyDeviceToDevice);

    dim3 ga((N_ + 127) / 128, B_);
    dim3 gu(D_ / 128, B_);
    dim3 gs(H_, B_);

    for (int t = 0; t < T_; t++) {
        // slot->feature attention
        ln_kernel<<<B_ * K_, 256>>>(slots, nullptr, ns_g, ns_b, sn);
        sgemm_sm(sn, Wq, nullptr, nullptr, q, B_ * K_, D_, D_, 0);
        zero_kernel<<<2, 256>>>(massp, B_ * K_);
        attn_kernel<<<ga, 128>>>(q, Kf, attnp, massp);
        updates_kernel<<<gu, 128>>>(attnp, Vf, massp, upd);

        // transformer block on sn
        ln_kernel<<<B_ * K_, 256>>>(sn, nullptr, b_ln1g + t * D_, b_ln1b + t * D_, h1);
        sgemm_sm(h1, b_Wqkv + (size_t)t * D_ * 3 * D_, b_bqkv + (size_t)t * 3 * D_,
                 nullptr, qkvp, B_ * K_, 3 * D_, D_, 0);
        slot_attn_kernel<<<gs, 128>>>(qkvp, op);
        sgemm_sm(op, b_Wo + (size_t)t * D_ * D_, b_bo + (size_t)t * D_,
                 sn, resid, B_ * K_, D_, D_, 0);                     // resid = sn + o@Wo + bo
        ln_kernel<<<B_ * K_, 256>>>(resid, nullptr, b_ln2g + t * D_, b_ln2b + t * D_, h2);
        sgemm_sm(h2, b_W1 + (size_t)t * D_ * 4 * D_, b_b1 + (size_t)t * 4 * D_,
                 nullptr, hid, B_ * K_, 4 * D_, D_, 1);              // gelu
        sgemm_sm(hid, b_W2 + (size_t)t * 4 * D_ * D_, b_b2 + (size_t)t * D_,
                 resid, resid, B_ * K_, D_, 4 * D_, 0);              // resid += mlp

        // slot update MLP
        ln_kernel<<<B_ * K_, 256>>>(upd, resid, mg, mb, h3);          // LN(updates + resid)
        sgemm_sm(h3, mW1, mb1, nullptr, hid, B_ * K_, 4 * D_, D_, 1); // gelu
        sgemm_sm(hid, mW2, mb2, slots, slots, B_ * K_, D_, 4 * D_, 0); // slots += ...
    }

    // final masks
    ln_kernel<<<B_ * K_, 256>>>(slots, nullptr, ns_g, ns_b, sn);
    sgemm_sm(sn, Wq, nullptr, nullptr, q, B_ * K_, D_, D_, 0);
    zero_kernel<<<2, 256>>>(massp, B_ * K_);
    attn_kernel<<<ga, 128>>>(q, Kf, attnp, massp);

    // outputs: slots [B,K,D] then masks [B,N,K]
    float* out = (float*)d_out;
    cudaMemcpyAsync(out, slots, SZ_BKD * sizeof(float), cudaMemcpyDeviceToDevice);
    if ((size_t)out_size >= SZ_BKD + (size_t)B_ * N_ * K_)
        cudaMemcpyAsync(out + SZ_BKD, attnp, (size_t)B_ * N_ * K_ * sizeof(float),
                        cudaMemcpyDeviceToDevice);
}

// round 4
// speedup vs baseline: 1.4185x; 1.4185x over previous
#include <cuda_runtime.h>
#include <math.h>

// ---------------- problem constants ----------------
#define D_   768
#define K_   12
#define B_   32
#define N_   1369
#define T_   3
#define H_   8
#define HD_  96
#define BNROWS (B_*N_)

#define SCALE_     0.03608439182435161f   // 768^-0.5
#define HSCALE_    0.10206207261596575f   // 96^-0.5
#define EPS_       1e-8f

// ---------------- scratch (device global, allocation-free) ----------------
static __host__ __device__ constexpr size_t SZ_BND = (size_t)B_*N_*D_;   // 33.6M
static __host__ __device__ constexpr size_t SZ_BKD = (size_t)B_*K_*D_;   // 294,912
static __host__ __device__ constexpr size_t SZ_DD  = (size_t)D_*D_;      // 589,824

static constexpr size_t O_FNORM = 0;
static constexpr size_t O_WKT   = O_FNORM + SZ_BND;
static constexpr size_t O_WQK   = O_WKT   + SZ_DD;
static constexpr size_t O_SLOTS = O_WQK   + SZ_DD;
static constexpr size_t O_SN    = O_SLOTS + SZ_BKD;
static constexpr size_t O_QK    = O_SN    + SZ_BKD;
static constexpr size_t O_U0    = O_QK    + SZ_BKD;
static constexpr size_t O_UPD   = O_U0    + SZ_BKD;
static constexpr size_t O_H1    = O_UPD   + SZ_BKD;
static constexpr size_t O_O     = O_H1    + SZ_BKD;
static constexpr size_t O_RESID = O_O     + SZ_BKD;
static constexpr size_t O_H2    = O_RESID + SZ_BKD;
static constexpr size_t O_H3    = O_H2    + SZ_BKD;
static constexpr size_t O_QKV   = O_H3    + SZ_BKD;                        // B*K*3D
static constexpr size_t O_HID   = O_QKV   + (size_t)B_*K_*3*D_;            // B*K*4D
static constexpr size_t O_ATTN  = O_HID   + (size_t)B_*K_*4*D_;            // B*N*K
static constexpr size_t O_MASS  = O_ATTN  + (size_t)B_*N_*K_;
static constexpr size_t TOTALF  = O_MASS + 512;

__device__ float g_buf[TOTALF];

// ---------------- LayerNorm (optionally fused 2-input add) ----------------
__global__ void ln_kernel(const float* __restrict__ x, const float* __restrict__ x2,
                          const float* __restrict__ g, const float* __restrict__ bta,
                          float* __restrict__ out)
{
    __shared__ float row[D_];
    __shared__ float red[256];
    int r = blockIdx.x;
    int tid = threadIdx.x;
    const float* xr = x + (size_t)r * D_;
    float s = 0.f;
    for (int i = tid; i < D_; i += 256) {
        float v = xr[i];
        if (x2) v += x2[(size_t)r * D_ + i];
        row[i] = v; s += v;
    }
    red[tid] = s; __syncthreads();
    for (int o = 128; o > 0; o >>= 1) { if (tid < o) red[tid] += red[tid + o]; __syncthreads(); }
    float mean = red[0] * (1.f / D_);
    __syncthreads();
    s = 0.f;
    for (int i = tid; i < D_; i += 256) { float d = row[i] - mean; s += d * d; }
    red[tid] = s; __syncthreads();
    for (int o = 128; o > 0; o >>= 1) { if (tid < o) red[tid] += red[tid + o]; __syncthreads(); }
    float rstd = rsqrtf(red[0] * (1.f / D_) + 1e-5f);
    for (int i = tid; i < D_; i += 256)
        out[(size_t)r * D_ + i] = (row[i] - mean) * rstd * g[i] + bta[i];
}

// ---------------- 768x768 transpose ----------------
__global__ void transpose_kernel(const float* __restrict__ in, float* __restrict__ out)
{
    __shared__ float t[32][33];
    int x = blockIdx.x * 32 + threadIdx.x;
    int y = blockIdx.y * 32 + threadIdx.y;
    #pragma unroll
    for (int j = 0; j < 32; j += 8) t[threadIdx.y + j][threadIdx.x] = in[(size_t)(y + j) * D_ + x];
    __syncthreads();
    x = blockIdx.y * 32 + threadIdx.x;
    y = blockIdx.x * 32 + threadIdx.y;
    #pragma unroll
    for (int j = 0; j < 32; j += 8) out[(size_t)(y + j) * D_ + x] = t[threadIdx.x][threadIdx.y + j];
}

// ---------------- tiled SGEMM: C = A[MxK] @ W[KxN] (+bias)(gelu)(+res) ----------------
template<int BM, int TM>
__global__ void sgemm_kernel(const float* __restrict__ A, const float* __restrict__ W,
                             const float* __restrict__ bias, const float* __restrict__ res,
                             float* __restrict__ C, int M, int N, int K, int act)
{
    constexpr int BN = 64, BK = 16, TN = 4;
    __shared__ float As[BK][BM + 4];
    __shared__ float Bs[BK][BN];
    int tid = threadIdx.x;
    int tx = tid & 15, ty = tid >> 4;
    int m0 = blockIdx.y * BM, n0 = blockIdx.x * BN;

    float acc[TM][TN];
    #pragma unroll
    for (int i = 0; i < TM; i++)
        #pragma unroll
        for (int j = 0; j < TN; j++) acc[i][j] = 0.f;

    for (int k0 = 0; k0 < K; k0 += BK) {
        #pragma unroll
        for (int i = tid; i < BM * BK / 4; i += 256) {
            int r = i >> 2, c4 = (i & 3) * 4;
            float4 v = make_float4(0.f, 0.f, 0.f, 0.f);
            if (m0 + r < M) v = *(const float4*)(A + (size_t)(m0 + r) * K + k0 + c4);
            As[c4 + 0][r] = v.x; As[c4 + 1][r] = v.y; As[c4 + 2][r] = v.z; As[c4 + 3][r] = v.w;
        }
        #pragma unroll
        for (int p = 0; p < 4; p++) {
            int r = (tid >> 6) + p * 4, c = tid & 63;
            Bs[r][c] = (n0 + c < N) ? W[(size_t)(k0 + r) * N + n0 + c] : 0.f;
        }
        __syncthreads();
        #pragma unroll
        for (int kk = 0; kk < BK; kk++) {
            float a[TM], bv[TN];
            #pragma unroll
            for (int i = 0; i < TM; i += 4) {
                float4 t4 = *(const float4*)&As[kk][ty * TM + i];
                a[i] = t4.x; a[i + 1] = t4.y; a[i + 2] = t4.z; a[i + 3] = t4.w;
            }
            float4 b4 = *(const float4*)&Bs[kk][tx * TN];
            bv[0] = b4.x; bv[1] = b4.y; bv[2] = b4.z; bv[3] = b4.w;
            #pragma unroll
            for (int i = 0; i < TM; i++)
                #pragma unroll
                for (int j = 0; j < TN; j++) acc[i][j] += a[i] * bv[j];
        }
        __syncthreads();
    }

    #pragma unroll
    for (int i = 0; i < TM; i++) {
        int m = m0 + ty * TM + i;
        if (m >= M) continue;
        #pragma unroll
        for (int j = 0; j < TN; j++) {
            int n = n0 + tx * TN + j;
            if (n >= N) continue;
            float v = acc[i][j];
            if (bias) v += bias[n];
            if (act)  v = 0.5f * v * (1.f + erff(v * 0.70710678118654752f));
            if (res)  v += res[(size_t)m * N + n];
            C[(size_t)m * N + n] = v;
        }
    }
}

// ---------------- logits + softmax(K) + mass; fn streamed directly ----------------
// grid (ceil(N/128), B), 128 threads; one thread per feature n.
__global__ void attn_kernel(const float* __restrict__ qk, const float* __restrict__ fn,
                            float* __restrict__ attn, float* __restrict__ mass)
{
    int b = blockIdx.y;
    int tid = threadIdx.x;
    int n0 = blockIdx.x * 128;
    int n = n0 + tid;
    __shared__ float qs[K_][D_];      // 36 KB
    __shared__ float kt[128][12];
    __shared__ float smass[K_];

    for (int i = tid; i < K_ * D_; i += 128) qs[i / D_][i % D_] = qk[(size_t)b * K_ * D_ + i];
    if (tid < K_) smass[tid] = 0.f;
    __syncthreads();

    float acc[K_];
    #pragma unroll
    for (int s = 0; s < K_; s++) acc[s] = 0.f;

    const float* Kb = fn + (size_t)b * N_ * D_;
    bool valid = (n < N_);

    for (int d0 = 0; d0 < D_; d0 += 8) {
        #pragma unroll
        for (int i = tid; i < 256; i += 128) {
            int r = i >> 1, c4 = (i & 1) * 4;
            float4 v = make_float4(0.f, 0.f, 0.f, 0.f);
            if (n0 + r < N_) v = *(const float4*)(Kb + (size_t)(n0 + r) * D_ + d0 + c4);
            kt[r][c4] = v.x; kt[r][c4 + 1] = v.y; kt[r][c4 + 2] = v.z; kt[r][c4 + 3] = v.w;
        }
        __syncthreads();
        if (valid) {
            #pragma unroll
            for (int c = 0; c < 8; c += 4) {
                float4 kv = *(const float4*)&kt[tid][c];
                #pragma unroll
                for (int s = 0; s < K_; s++) {
                    float4 qv = *(const float4*)&qs[s][d0 + c];
                    acc[s] += qv.x * kv.x + qv.y * kv.y + qv.z * kv.z + qv.w * kv.w;
                }
            }
        }
        __syncthreads();
    }

    if (valid) {
        float mx = -1e30f;
        #pragma unroll
        for (int s = 0; s < K_; s++) { acc[s] *= SCALE_; mx = fmaxf(mx, acc[s]); }
        float ssum = 0.f;
        #pragma unroll
        for (int s = 0; s < K_; s++) { float e = expf(acc[s] - mx); acc[s] = e; ssum += e; }
        float inv = 1.f / ssum;
        float* ap = attn + ((size_t)b * N_ + n) * K_;
        #pragma unroll
        for (int s = 0; s < K_; s++) {
            float a = acc[s] * inv;
            ap[s] = a;
            atomicAdd(&smass[s], a);
        }
    }
    __syncthreads();
    if (tid < K_) atomicAdd(&mass[b * K_ + tid], smass[tid]);
}

// ---------------- u0 = (attn^T @ fn) / max(mass, EPS) ----------------
// grid (D/128, B), 128 threads; thread owns one d.
__global__ void updates_kernel(const float* __restrict__ attn, const float* __restrict__ fn,
                               const float* __restrict__ mass, float* __restrict__ u0)
{
    int b = blockIdx.y;
    int d = blockIdx.x * 128 + threadIdx.x;
    __shared__ float as_[32][K_];
    float acc[K_];
    #pragma unroll
    for (int s = 0; s < K_; s++) acc[s] = 0.f;
    const float* Vb = fn + (size_t)b * N_ * D_;
    const float* Ab = attn + (size_t)b * N_ * K_;
    for (int n0 = 0; n0 < N_; n0 += 32) {
        int lim = min(32, N_ - n0);
        for (int i = threadIdx.x; i < lim * K_; i += 128) as_[i / K_][i % K_] = Ab[(size_t)n0 * K_ + i];
        __syncthreads();
        for (int r = 0; r < lim; r++) {
            float v = Vb[(size_t)(n0 + r) * D_ + d];
            #pragma unroll
            for (int s = 0; s < K_; s++) acc[s] += as_[r][s] * v;
        }
        __syncthreads();
    }
    #pragma unroll
    for (int s = 0; s < K_; s++)
        u0[((size_t)b * K_ + s) * D_ + d] = acc[s] / fmaxf(mass[b * K_ + s], EPS_);
}

// ---------------- transformer block self-attention over K=12 slots ----------------
__global__ void slot_attn_kernel(const float* __restrict__ qkv, float* __restrict__ o)
{
    int h = blockIdx.x, b = blockIdx.y;
    __shared__ float qh[K_][HD_], kh[K_][HD_], vh[K_][HD_];
    __shared__ float sc[K_][K_ + 1];
    int tid = threadIdx.x;
    for (int i = tid; i < K_ * HD_; i += 128) {
        int s = i / HD_, c = i % HD_;
        const float* base = qkv + ((size_t)(b * K_ + s)) * (3 * D_) + h * HD_ + c;
        qh[s][c] = base[0]; kh[s][c] = base[D_]; vh[s][c] = base[2 * D_];
    }
    __syncthreads();
    for (int i = tid; i < K_ * K_; i += 128) {
        int si = i / K_, sj = i % K_;
        float d = 0.f;
        #pragma unroll 8
        for (int c = 0; c < HD_; c++) d += qh[si][c] * kh[sj][c];
        sc[si][sj] = d * HSCALE_;
    }
    __syncthreads();
    if (tid < K_) {
        float mx = -1e30f;
        for (int j = 0; j < K_; j++) mx = fmaxf(mx, sc[tid][j]);
        float s = 0.f;
        for (int j = 0; j < K_; j++) { float e = expf(sc[tid][j] - mx); sc[tid][j] = e; s += e; }
        float inv = 1.f / s;
        for (int j = 0; j < K_; j++) sc[tid][j] *= inv;
    }
    __syncthreads();
    for (int i = tid; i < K_ * HD_; i += 128) {
        int s = i / HD_, c = i % HD_;
        float acc = 0.f;
        #pragma unroll
        for (int j = 0; j < K_; j++) acc += sc[s][j] * vh[j][c];
        o[((size_t)(b * K_ + s)) * D_ + h * HD_ + c] = acc;
    }
}

__global__ void zero_kernel(float* __restrict__ p, int n)
{
    int i = blockIdx.x * 256 + threadIdx.x;
    if (i < n) p[i] = 0.f;
}

// ---------------- host-side launch helpers ----------------
static inline void sgemm_sm(const float* A, const float* W, const float* bias, const float* res,
                            float* C, int M, int N, int K, int act)
{
    dim3 g((N + 63) / 64, (M + 63) / 64);
    sgemm_kernel<64, 4><<<g, 256>>>(A, W, bias, res, C, M, N, K, act);
}

extern "C" void kernel_launch(void* const* d_in, const int* in_sizes, int n_in,
                              void* d_out, int out_size)
{
    const float* features   = (const float*)d_in[0];
    const float* slots_init = (const float*)d_in[1];
    const float* nf_g = (const float*)d_in[2];
    const float* nf_b = (const float*)d_in[3];
    const float* ns_g = (const float*)d_in[4];
    const float* ns_b = (const float*)d_in[5];
    const float* Wq   = (const float*)d_in[6];
    const float* Wk   = (const float*)d_in[7];
    const float* Wv   = (const float*)d_in[8];
    const float* mg   = (const float*)d_in[9];
    const float* mb   = (const float*)d_in[10];
    const float* mW1  = (const float*)d_in[11];
    const float* mb1  = (const float*)d_in[12];
    const float* mW2  = (const float*)d_in[13];
    const float* mb2  = (const float*)d_in[14];
    const float* b_ln1g = (const float*)d_in[15];
    const float* b_ln1b = (const float*)d_in[16];
    const float* b_Wqkv = (const float*)d_in[17];
    const float* b_bqkv = (const float*)d_in[18];
    const float* b_Wo   = (const float*)d_in[19];
    const float* b_bo   = (const float*)d_in[20];
    const float* b_ln2g = (const float*)d_in[21];
    const float* b_ln2b = (const float*)d_in[22];
    const float* b_W1   = (const float*)d_in[23];
    const float* b_b1   = (const float*)d_in[24];
    const float* b_W2   = (const float*)d_in[25];
    const float* b_b2   = (const float*)d_in[26];

    float* buf = nullptr;
    cudaGetSymbolAddress((void**)&buf, g_buf);
    float* fnorm = buf + O_FNORM;
    float* WkT   = buf + O_WKT;
    float* Wqk   = buf + O_WQK;
    float* slots = buf + O_SLOTS;
    float* sn    = buf + O_SN;
    float* qk    = buf + O_QK;
    float* u0    = buf + O_U0;
    float* upd   = buf + O_UPD;
    float* h1    = buf + O_H1;
    float* op    = buf + O_O;
    float* resid = buf + O_RESID;
    float* h2    = buf + O_H2;
    float* h3    = buf + O_H3;
    float* qkvp  = buf + O_QKV;
    float* hid   = buf + O_HID;
    float* attnp = buf + O_ATTN;
    float* massp = buf + O_MASS;

    // ---- loop-invariant precompute ----
    // fn = LN(features); Wqk = Wq @ Wk^T  (replaces the two huge projections)
    ln_kernel<<<BNROWS, 256>>>(features, nullptr, nf_g, nf_b, fnorm);
    {
        dim3 gt(24, 24); dim3 bt(32, 8);
        transpose_kernel<<<gt, bt>>>(Wk, WkT);
    }
    sgemm_sm(Wq, WkT, nullptr, nullptr, Wqk, D_, D_, D_, 0);
    cudaMemcpyAsync(slots, slots_init, SZ_BKD * sizeof(float), cudaMemcpyDeviceToDevice);

    dim3 ga((N_ + 127) / 128, B_);
    dim3 gu(D_ / 128, B_);
    dim3 gs(H_, B_);

    for (int t = 0; t < T_; t++) {
        // slot->feature attention (projection-free: qk = sn @ Wqk, stream fn)
        ln_kernel<<<B_ * K_, 256>>>(slots, nullptr, ns_g, ns_b, sn);
        sgemm_sm(sn, Wqk, nullptr, nullptr, qk, B_ * K_, D_, D_, 0);
        zero_kernel<<<2, 256>>>(massp, B_ * K_);
        attn_kernel<<<ga, 128>>>(qk, fnorm, attnp, massp);
        updates_kernel<<<gu, 128>>>(attnp, fnorm, massp, u0);
        sgemm_sm(u0, Wv, nullptr, nullptr, upd, B_ * K_, D_, D_, 0);   // updates = u0 @ Wv

        // transformer block on sn
        ln_kernel<<<B_ * K_, 256>>>(sn, nullptr, b_ln1g + t * D_, b_ln1b + t * D_, h1);
        sgemm_sm(h1, b_Wqkv + (size_t)t * D_ * 3 * D_, b_bqkv + (size_t)t * 3 * D_,
                 nullptr, qkvp, B_ * K_, 3 * D_, D_, 0);
        slot_attn_kernel<<<gs, 128>>>(qkvp, op);
        sgemm_sm(op, b_Wo + (size_t)t * D_ * D_, b_bo + (size_t)t * D_,
                 sn, resid, B_ * K_, D_, D_, 0);                     // resid = sn + o@Wo + bo
        ln_kernel<<<B_ * K_, 256>>>(resid, nullptr, b_ln2g + t * D_, b_ln2b + t * D_, h2);
        sgemm_sm(h2, b_W1 + (size_t)t * D_ * 4 * D_, b_b1 + (size_t)t * 4 * D_,
                 nullptr, hid, B_ * K_, 4 * D_, D_, 1);              // gelu
        sgemm_sm(hid, b_W2 + (size_t)t * 4 * D_ * D_, b_b2 + (size_t)t * D_,
                 resid, resid, B_ * K_, D_, 4 * D_, 0);              // resid += mlp

        // slot update MLP
        ln_kernel<<<B_ * K_, 256>>>(upd, resid, mg, mb, h3);          // LN(updates + resid)
        sgemm_sm(h3, mW1, mb1, nullptr, hid, B_ * K_, 4 * D_, D_, 1); // gelu
        sgemm_sm(hid, mW2, mb2, slots, slots, B_ * K_, D_, 4 * D_, 0); // slots += ...
    }

    // final masks
    ln_kernel<<<B_ * K_, 256>>>(slots, nullptr, ns_g, ns_b, sn);
    sgemm_sm(sn, Wqk, nullptr, nullptr, qk, B_ * K_, D_, D_, 0);
    zero_kernel<<<2, 256>>>(massp, B_ * K_);
    attn_kernel<<<ga, 128>>>(qk, fnorm, attnp, massp);

    // outputs: slots [B,K,D] then masks [B,N,K]
    float* out = (float*)d_out;
    cudaMemcpyAsync(out, slots, SZ_BKD * sizeof(float), cudaMemcpyDeviceToDevice);
    if ((size_t)out_size >= SZ_BKD + (size_t)B_ * N_ * K_)
        cudaMemcpyAsync(out + SZ_BKD, attnp, (size_t)B_ * N_ * K_ * sizeof(float),
                        cudaMemcpyDeviceToDevice);
}

// round 5
// speedup vs baseline: 2.2613x; 1.5941x over previous
#include <cuda_runtime.h>
#include <math.h>

// ---------------- problem constants ----------------
#define D_   768
#define K_   12
#define B_   32
#define N_   1369
#define T_   3
#define H_   8
#define HD_  96
#define BNROWS (B_*N_)

#define SCALE_     0.03608439182435161f   // 768^-0.5
#define HSCALE_    0.10206207261596575f   // 96^-0.5
#define EPS_       1e-8f

// ---------------- scratch (device global, allocation-free) ----------------
static __host__ __device__ constexpr size_t SZ_BND = (size_t)B_*N_*D_;   // 33.6M
static __host__ __device__ constexpr size_t SZ_BKD = (size_t)B_*K_*D_;   // 294,912
static __host__ __device__ constexpr size_t SZ_DD  = (size_t)D_*D_;      // 589,824

static constexpr size_t O_FNORM = 0;
static constexpr size_t O_WKT   = O_FNORM + SZ_BND;
static constexpr size_t O_WQK   = O_WKT   + SZ_DD;
static constexpr size_t O_SLOTS = O_WQK   + SZ_DD;
static constexpr size_t O_SN    = O_SLOTS + SZ_BKD;
static constexpr size_t O_QK    = O_SN    + SZ_BKD;
static constexpr size_t O_U0    = O_QK    + SZ_BKD;
static constexpr size_t O_UPD   = O_U0    + SZ_BKD;
static constexpr size_t O_H1    = O_UPD   + SZ_BKD;
static constexpr size_t O_O     = O_H1    + SZ_BKD;
static constexpr size_t O_RESID = O_O     + SZ_BKD;
static constexpr size_t O_H2    = O_RESID + SZ_BKD;
static constexpr size_t O_H3    = O_H2    + SZ_BKD;
static constexpr size_t O_QKV   = O_H3    + SZ_BKD;                        // B*K*3D
static constexpr size_t O_HID   = O_QKV   + (size_t)B_*K_*3*D_;            // B*K*4D
static constexpr size_t O_ATTN  = O_HID   + (size_t)B_*K_*4*D_;            // B*N*K
static constexpr size_t O_MASS  = O_ATTN  + (size_t)B_*N_*K_;
static constexpr size_t TOTALF  = O_MASS + 512;

__device__ float g_buf[TOTALF];

// ---------------- LayerNorm (optionally fused 2-input add) ----------------
__global__ void ln_kernel(const float* __restrict__ x, const float* __restrict__ x2,
                          const float* __restrict__ g, const float* __restrict__ bta,
                          float* __restrict__ out)
{
    __shared__ float row[D_];
    __shared__ float red[256];
    int r = blockIdx.x;
    int tid = threadIdx.x;
    const float* xr = x + (size_t)r * D_;
    float s = 0.f;
    for (int i = tid; i < D_; i += 256) {
        float v = xr[i];
        if (x2) v += x2[(size_t)r * D_ + i];
        row[i] = v; s += v;
    }
    red[tid] = s; __syncthreads();
    for (int o = 128; o > 0; o >>= 1) { if (tid < o) red[tid] += red[tid + o]; __syncthreads(); }
    float mean = red[0] * (1.f / D_);
    __syncthreads();
    s = 0.f;
    for (int i = tid; i < D_; i += 256) { float d = row[i] - mean; s += d * d; }
    red[tid] = s; __syncthreads();
    for (int o = 128; o > 0; o >>= 1) { if (tid < o) red[tid] += red[tid + o]; __syncthreads(); }
    float rstd = rsqrtf(red[0] * (1.f / D_) + 1e-5f);
    for (int i = tid; i < D_; i += 256)
        out[(size_t)r * D_ + i] = (row[i] - mean) * rstd * g[i] + bta[i];
}

// ---------------- 768x768 transpose ----------------
__global__ void transpose_kernel(const float* __restrict__ in, float* __restrict__ out)
{
    __shared__ float t[32][33];
    int x = blockIdx.x * 32 + threadIdx.x;
    int y = blockIdx.y * 32 + threadIdx.y;
    #pragma unroll
    for (int j = 0; j < 32; j += 8) t[threadIdx.y + j][threadIdx.x] = in[(size_t)(y + j) * D_ + x];
    __syncthreads();
    x = blockIdx.y * 32 + threadIdx.x;
    y = blockIdx.x * 32 + threadIdx.y;
    #pragma unroll
    for (int j = 0; j < 32; j += 8) out[(size_t)(y + j) * D_ + x] = t[threadIdx.x][threadIdx.y + j];
}

// ---------------- slot GEMM: C[Mx N] = A[MxK] @ W[KxN] (+bias)(gelu)(+res) ----------------
// Tuned for small M: block covers 48 contiguous rows x 64 cols. M % 48 == 0,
// N % 64 == 0, K % 64 == 0. grid (N/64, M/48), 256 threads.
// Thread: nq = tid&15 -> 4 cols (float4); rg = tid>>4 -> 3 rows.
__global__ void slotgemm_kernel(const float* __restrict__ A, const float* __restrict__ W,
                                const float* __restrict__ bias, const float* __restrict__ res,
                                float* __restrict__ C, int N, int K, int act)
{
    __shared__ float As[48][68];
    __shared__ float Ws[64][68];
    int tid = threadIdx.x;
    int nq = tid & 15;
    int rg = tid >> 4;
    int n0 = blockIdx.x * 64;
    int r0 = blockIdx.y * 48;

    float4 acc0 = make_float4(0.f,0.f,0.f,0.f);
    float4 acc1 = make_float4(0.f,0.f,0.f,0.f);
    float4 acc2 = make_float4(0.f,0.f,0.f,0.f);

    for (int k0 = 0; k0 < K; k0 += 64) {
        // stage A chunk: 48 x 64 = 768 float4
        #pragma unroll
        for (int i = 0; i < 3; i++) {
            int f = tid + i * 256;
            int r = f >> 4, kq = f & 15;
            float4 v = *(const float4*)(A + (size_t)(r0 + r) * K + k0 + kq * 4);
            *(float4*)&As[r][kq * 4] = v;
        }
        // stage W tile: 64 x 64 = 1024 float4
        #pragma unroll
        for (int i = 0; i < 4; i++) {
            int f = tid + i * 256;
            int r = f >> 4, kq = f & 15;
            float4 v = *(const float4*)(W + (size_t)(k0 + r) * N + n0 + kq * 4);
            *(float4*)&Ws[r][kq * 4] = v;
        }
        __syncthreads();
        #pragma unroll
        for (int k = 0; k < 64; k += 4) {
            float4 a0 = *(const float4*)&As[rg * 3 + 0][k];
            float4 a1 = *(const float4*)&As[rg * 3 + 1][k];
            float4 a2 = *(const float4*)&As[rg * 3 + 2][k];
            #pragma unroll
            for (int j = 0; j < 4; j++) {
                float4 wv = *(const float4*)&Ws[k + j][nq * 4];
                float e0 = (j == 0) ? a0.x : (j == 1) ? a0.y : (j == 2) ? a0.z : a0.w;
                float e1 = (j == 0) ? a1.x : (j == 1) ? a1.y : (j == 2) ? a1.z : a1.w;
                float e2 = (j == 0) ? a2.x : (j == 1) ? a2.y : (j == 2) ? a2.z : a2.w;
                acc0.x += e0 * wv.x; acc0.y += e0 * wv.y; acc0.z += e0 * wv.z; acc0.w += e0 * wv.w;
                acc1.x += e1 * wv.x; acc1.y += e1 * wv.y; acc1.z += e1 * wv.z; acc1.w += e1 * wv.w;
                acc2.x += e2 * wv.x; acc2.y += e2 * wv.y; acc2.z += e2 * wv.z; acc2.w += e2 * wv.w;
            }
        }
        __syncthreads();
    }

    // epilogue
    float out[3][4] = {{acc0.x,acc0.y,acc0.z,acc0.w},
                       {acc1.x,acc1.y,acc1.z,acc1.w},
                       {acc2.x,acc2.y,acc2.z,acc2.w}};
    #pragma unroll
    for (int i = 0; i < 3; i++) {
        int m = r0 + rg * 3 + i;
        int n = n0 + nq * 4;
        float4 v = *(float4*)out[i];
        if (bias) {
            float4 bv = *(const float4*)(bias + n);
            v.x += bv.x; v.y += bv.y; v.z += bv.z; v.w += bv.w;
        }
        if (act) {
            v.x = 0.5f * v.x * (1.f + erff(v.x * 0.70710678118654752f));
            v.y = 0.5f * v.y * (1.f + erff(v.y * 0.70710678118654752f));
            v.z = 0.5f * v.z * (1.f + erff(v.z * 0.70710678118654752f));
            v.w = 0.5f * v.w * (1.f + erff(v.w * 0.70710678118654752f));
        }
        if (res) {
            float4 rv = *(const float4*)(res + (size_t)m * N + n);
            v.x += rv.x; v.y += rv.y; v.z += rv.z; v.w += rv.w;
        }
        *(float4*)(C + (size_t)m * N + n) = v;
    }
}

// ---------------- logits + softmax(K) + mass; fn streamed directly ----------------
__global__ void attn_kernel(const float* __restrict__ qk, const float* __restrict__ fn,
                            float* __restrict__ attn, float* __restrict__ mass)
{
    int b = blockIdx.y;
    int tid = threadIdx.x;
    int n0 = blockIdx.x * 128;
    int n = n0 + tid;
    __shared__ float qs[K_][D_];      // 36 KB
    __shared__ float kt[128][12];
    __shared__ float smass[K_];

    for (int i = tid; i < K_ * D_; i += 128) qs[i / D_][i % D_] = qk[(size_t)b * K_ * D_ + i];
    if (tid < K_) smass[tid] = 0.f;
    __syncthreads();

    float acc[K_];
    #pragma unroll
    for (int s = 0; s < K_; s++) acc[s] = 0.f;

    const float* Kb = fn + (size_t)b * N_ * D_;
    bool valid = (n < N_);

    for (int d0 = 0; d0 < D_; d0 += 8) {
        #pragma unroll
        for (int i = tid; i < 256; i += 128) {
            int r = i >> 1, c4 = (i & 1) * 4;
            float4 v = make_float4(0.f, 0.f, 0.f, 0.f);
            if (n0 + r < N_) v = *(const float4*)(Kb + (size_t)(n0 + r) * D_ + d0 + c4);
            kt[r][c4] = v.x; kt[r][c4 + 1] = v.y; kt[r][c4 + 2] = v.z; kt[r][c4 + 3] = v.w;
        }
        __syncthreads();
        if (valid) {
            #pragma unroll
            for (int c = 0; c < 8; c += 4) {
                float4 kv = *(const float4*)&kt[tid][c];
                #pragma unroll
                for (int s = 0; s < K_; s++) {
                    float4 qv = *(const float4*)&qs[s][d0 + c];
                    acc[s] += qv.x * kv.x + qv.y * kv.y + qv.z * kv.z + qv.w * kv.w;
                }
            }
        }
        __syncthreads();
    }

    if (valid) {
        float mx = -1e30f;
        #pragma unroll
        for (int s = 0; s < K_; s++) { acc[s] *= SCALE_; mx = fmaxf(mx, acc[s]); }
        float ssum = 0.f;
        #pragma unroll
        for (int s = 0; s < K_; s++) { float e = expf(acc[s] - mx); acc[s] = e; ssum += e; }
        float inv = 1.f / ssum;
        float* ap = attn + ((size_t)b * N_ + n) * K_;
        #pragma unroll
        for (int s = 0; s < K_; s++) {
            float a = acc[s] * inv;
            ap[s] = a;
            atomicAdd(&smass[s], a);
        }
    }
    __syncthreads();
    if (tid < K_) atomicAdd(&mass[b * K_ + tid], smass[tid]);
}

// ---------------- u0 = (attn^T @ fn) / max(mass, EPS) ----------------
__global__ void updates_kernel(const float* __restrict__ attn, const float* __restrict__ fn,
                               const float* __restrict__ mass, float* __restrict__ u0)
{
    int b = blockIdx.y;
    int d = blockIdx.x * 128 + threadIdx.x;
    __shared__ float as_[32][K_];
    float acc[K_];
    #pragma unroll
    for (int s = 0; s < K_; s++) acc[s] = 0.f;
    const float* Vb = fn + (size_t)b * N_ * D_;
    const float* Ab = attn + (size_t)b * N_ * K_;
    for (int n0 = 0; n0 < N_; n0 += 32) {
        int lim = min(32, N_ - n0);
        for (int i = threadIdx.x; i < lim * K_; i += 128) as_[i / K_][i % K_] = Ab[(size_t)n0 * K_ + i];
        __syncthreads();
        for (int r = 0; r < lim; r++) {
            float v = Vb[(size_t)(n0 + r) * D_ + d];
            #pragma unroll
            for (int s = 0; s < K_; s++) acc[s] += as_[r][s] * v;
        }
        __syncthreads();
    }
    #pragma unroll
    for (int s = 0; s < K_; s++)
        u0[((size_t)b * K_ + s) * D_ + d] = acc[s] / fmaxf(mass[b * K_ + s], EPS_);
}

// ---------------- transformer block self-attention over K=12 slots ----------------
__global__ void slot_attn_kernel(const float* __restrict__ qkv, float* __restrict__ o)
{
    int h = blockIdx.x, b = blockIdx.y;
    __shared__ float qh[K_][HD_], kh[K_][HD_], vh[K_][HD_];
    __shared__ float sc[K_][K_ + 1];
    int tid = threadIdx.x;
    for (int i = tid; i < K_ * HD_; i += 128) {
        int s = i / HD_, c = i % HD_;
        const float* base = qkv + ((size_t)(b * K_ + s)) * (3 * D_) + h * HD_ + c;
        qh[s][c] = base[0]; kh[s][c] = base[D_]; vh[s][c] = base[2 * D_];
    }
    __syncthreads();
    for (int i = tid; i < K_ * K_; i += 128) {
        int si = i / K_, sj = i % K_;
        float d = 0.f;
        #pragma unroll 8
        for (int c = 0; c < HD_; c++) d += qh[si][c] * kh[sj][c];
        sc[si][sj] = d * HSCALE_;
    }
    __syncthreads();
    if (tid < K_) {
        float mx = -1e30f;
        for (int j = 0; j < K_; j++) mx = fmaxf(mx, sc[tid][j]);
        float s = 0.f;
        for (int j = 0; j < K_; j++) { float e = expf(sc[tid][j] - mx); sc[tid][j] = e; s += e; }
        float inv = 1.f / s;
        for (int j = 0; j < K_; j++) sc[tid][j] *= inv;
    }
    __syncthreads();
    for (int i = tid; i < K_ * HD_; i += 128) {
        int s = i / HD_, c = i % HD_;
        float acc = 0.f;
        #pragma unroll
        for (int j = 0; j < K_; j++) acc += sc[s][j] * vh[j][c];
        o[((size_t)(b * K_ + s)) * D_ + h * HD_ + c] = acc;
    }
}

__global__ void zero_kernel(float* __restrict__ p, int n)
{
    int i = blockIdx.x * 256 + threadIdx.x;
    if (i < n) p[i] = 0.f;
}

// ---------------- host-side launch helper ----------------
static inline void slotgemm(const float* A, const float* W, const float* bias, const float* res,
                            float* C, int M, int N, int K, int act)
{
    dim3 g(N / 64, M / 48);
    slotgemm_kernel<<<g, 256>>>(A, W, bias, res, C, N, K, act);
}

extern "C" void kernel_launch(void* const* d_in, const int* in_sizes, int n_in,
                              void* d_out, int out_size)
{
    const float* features   = (const float*)d_in[0];
    const float* slots_init = (const float*)d_in[1];
    const float* nf_g = (const float*)d_in[2];
    const float* nf_b = (const float*)d_in[3];
    const float* ns_g = (const float*)d_in[4];
    const float* ns_b = (const float*)d_in[5];
    const float* Wq   = (const float*)d_in[6];
    const float* Wk   = (const float*)d_in[7];
    const float* Wv   = (const float*)d_in[8];
    const float* mg   = (const float*)d_in[9];
    const float* mb   = (const float*)d_in[10];
    const float* mW1  = (const float*)d_in[11];
    const float* mb1  = (const float*)d_in[12];
    const float* mW2  = (const float*)d_in[13];
    const float* mb2  = (const float*)d_in[14];
    const float* b_ln1g = (const float*)d_in[15];
    const float* b_ln1b = (const float*)d_in[16];
    const float* b_Wqkv = (const float*)d_in[17];
    const float* b_bqkv = (const float*)d_in[18];
    const float* b_Wo   = (const float*)d_in[19];
    const float* b_bo   = (const float*)d_in[20];
    const float* b_ln2g = (const float*)d_in[21];
    const float* b_ln2b = (const float*)d_in[22];
    const float* b_W1   = (const float*)d_in[23];
    const float* b_b1   = (const float*)d_in[24];
    const float* b_W2   = (const float*)d_in[25];
    const float* b_b2   = (const float*)d_in[26];

    float* buf = nullptr;
    cudaGetSymbolAddress((void**)&buf, g_buf);
    float* fnorm = buf + O_FNORM;
    float* WkT   = buf + O_WKT;
    float* Wqk   = buf + O_WQK;
    float* slots = buf + O_SLOTS;
    float* sn    = buf + O_SN;
    float* qk    = buf + O_QK;
    float* u0    = buf + O_U0;
    float* upd   = buf + O_UPD;
    float* h1    = buf + O_H1;
    float* op    = buf + O_O;
    float* resid = buf + O_RESID;
    float* h2    = buf + O_H2;
    float* h3    = buf + O_H3;
    float* qkvp  = buf + O_QKV;
    float* hid   = buf + O_HID;
    float* attnp = buf + O_ATTN;
    float* massp = buf + O_MASS;

    // ---- loop-invariant precompute ----
    ln_kernel<<<BNROWS, 256>>>(features, nullptr, nf_g, nf_b, fnorm);
    {
        dim3 gt(24, 24); dim3 bt(32, 8);
        transpose_kernel<<<gt, bt>>>(Wk, WkT);
    }
    slotgemm(Wq, WkT, nullptr, nullptr, Wqk, D_, D_, D_, 0);  // Wqk = Wq @ Wk^T
    cudaMemcpyAsync(slots, slots_init, SZ_BKD * sizeof(float), cudaMemcpyDeviceToDevice);

    dim3 ga((N_ + 127) / 128, B_);
    dim3 gu(D_ / 128, B_);
    dim3 gs(H_, B_);

    for (int t = 0; t < T_; t++) {
        // slot->feature attention (projection-free: qk = sn @ Wqk, stream fn)
        ln_kernel<<<B_ * K_, 256>>>(slots, nullptr, ns_g, ns_b, sn);
        slotgemm(sn, Wqk, nullptr, nullptr, qk, B_ * K_, D_, D_, 0);
        zero_kernel<<<2, 256>>>(massp, B_ * K_);
        attn_kernel<<<ga, 128>>>(qk, fnorm, attnp, massp);
        updates_kernel<<<gu, 128>>>(attnp, fnorm, massp, u0);
        slotgemm(u0, Wv, nullptr, nullptr, upd, B_ * K_, D_, D_, 0);   // updates = u0 @ Wv

        // transformer block on sn
        ln_kernel<<<B_ * K_, 256>>>(sn, nullptr, b_ln1g + t * D_, b_ln1b + t * D_, h1);
        slotgemm(h1, b_Wqkv + (size_t)t * D_ * 3 * D_, b_bqkv + (size_t)t * 3 * D_,
                 nullptr, qkvp, B_ * K_, 3 * D_, D_, 0);
        slot_attn_kernel<<<gs, 128>>>(qkvp, op);
        slotgemm(op, b_Wo + (size_t)t * D_ * D_, b_bo + (size_t)t * D_,
                 sn, resid, B_ * K_, D_, D_, 0);                     // resid = sn + o@Wo + bo
        ln_kernel<<<B_ * K_, 256>>>(resid, nullptr, b_ln2g + t * D_, b_ln2b + t * D_, h2);
        slotgemm(h2, b_W1 + (size_t)t * D_ * 4 * D_, b_b1 + (size_t)t * 4 * D_,
                 nullptr, hid, B_ * K_, 4 * D_, D_, 1);              // gelu
        slotgemm(hid, b_W2 + (size_t)t * 4 * D_ * D_, b_b2 + (size_t)t * D_,
                 resid, resid, B_ * K_, D_, 4 * D_, 0);              // resid += mlp

        // slot update MLP
        ln_kernel<<<B_ * K_, 256>>>(upd, resid, mg, mb, h3);          // LN(updates + resid)
        slotgemm(h3, mW1, mb1, nullptr, hid, B_ * K_, 4 * D_, D_, 1); // gelu
        slotgemm(hid, mW2, mb2, slots, slots, B_ * K_, D_, 4 * D_, 0); // slots += ...
    }

    // final masks
    ln_kernel<<<B_ * K_, 256>>>(slots, nullptr, ns_g, ns_b, sn);
    slotgemm(sn, Wqk, nullptr, nullptr, qk, B_ * K_, D_, D_, 0);
    zero_kernel<<<2, 256>>>(massp, B_ * K_);
    attn_kernel<<<ga, 128>>>(qk, fnorm, attnp, massp);

    // outputs: slots [B,K,D] then masks [B,N,K]
    float* out = (float*)d_out;
    cudaMemcpyAsync(out, slots, SZ_BKD * sizeof(float), cudaMemcpyDeviceToDevice);
    if ((size_t)out_size >= SZ_BKD + (size_t)B_ * N_ * K_)
        cudaMemcpyAsync(out + SZ_BKD, attnp, (size_t)B_ * N_ * K_ * sizeof(float),
                        cudaMemcpyDeviceToDevice);
}